// round 4
// baseline (speedup 1.0000x reference)
#include <cuda_runtime.h>
#include <cstdint>

// x [4,512,128] f32, y [512,128] f32 -> out [4,512,512,3] f32 (cos, L1, L2)
#define R_TOTAL 2048
#define C_TOTAL 512
#define D_DIM   128

#define BM 32
#define BN 32
#define LDW (D_DIM + 4)                 // 132 words/row: tx*132 % 32 = tx*4 -> conflict-free
#define SMEM_WORDS ((BM + BN) * LDW)    // 64 * 132 = 8448 words = 33792 B
#define SMEM_BYTES (SMEM_WORDS * 4)

typedef unsigned long long u64;
struct __align__(16) ull2 { u64 x, y; };

// ---------------- precomputed norms ----------------
__device__ float g_xsq[R_TOTAL];
__device__ float g_xrn[R_TOTAL];
__device__ float g_ysq[C_TOTAL];
__device__ float g_yrn[C_TOTAL];

__global__ void norms_kernel(const float* __restrict__ x,
                             const float* __restrict__ y) {
    int w    = (blockIdx.x * blockDim.x + threadIdx.x) >> 5;
    int lane = threadIdx.x & 31;
    if (w >= R_TOTAL + C_TOTAL) return;
    const float* p = (w < R_TOTAL) ? (x + (size_t)w * D_DIM)
                                   : (y + (size_t)(w - R_TOTAL) * D_DIM);
    float4 v = reinterpret_cast<const float4*>(p)[lane];
    float s = v.x * v.x + v.y * v.y + v.z * v.z + v.w * v.w;
    #pragma unroll
    for (int o = 16; o > 0; o >>= 1) s += __shfl_xor_sync(0xFFFFFFFFu, s, o);
    if (lane == 0) {
        float r = rsqrtf(s);
        if (w < R_TOTAL) { g_xsq[w] = s; g_xrn[w] = r; }
        else             { g_ysq[w - R_TOTAL] = s; g_yrn[w - R_TOTAL] = r; }
    }
}

// ---------------- packed f32x2 helpers ----------------
__device__ __forceinline__ u64 ffma2(u64 a, u64 b, u64 c) {
    u64 d;
    asm("fma.rn.f32x2 %0, %1, %2, %3;" : "=l"(d) : "l"(a), "l"(b), "l"(c));
    return d;
}
__device__ __forceinline__ u64 fadd2(u64 a, u64 b) {
    u64 d;
    asm("add.rn.f32x2 %0, %1, %2;" : "=l"(d) : "l"(a), "l"(b));
    return d;
}
__device__ __forceinline__ float f2lo(u64 d) { return __uint_as_float((unsigned)(d & 0xFFFFFFFFu)); }
__device__ __forceinline__ float f2hi(u64 d) { return __uint_as_float((unsigned)(d >> 32)); }

// ---------------- main distance kernel ----------------
// 128 threads: tx = t&15 (2 cols, stride 16), ty = t>>4 (4 rows, stride 8)
__global__ void __launch_bounds__(128, 6)
dist_kernel(const float* __restrict__ x, const float* __restrict__ y,
            float* __restrict__ out) {
    __shared__ __align__(16) float sm[SMEM_WORDS];
    float* xs = sm;                 // 32 rows x 132
    float* ys = sm + BM * LDW;      // 32 rows x 132

    const int R0 = blockIdx.x * BM;      // grid.x = 64
    const int C0 = blockIdx.y * BN;      // grid.y = 16
    const int t  = threadIdx.x;
    const int tx = t & 15;
    const int ty = t >> 4;

    // ---- stage full-D tiles: 64 rows x 128 cols = 2048 float4 / 128 thr = 16 each
    #pragma unroll
    for (int s = 0; s < 16; s++) {
        int idx  = t + 128 * s;          // 0..2047
        int row  = idx >> 5;             // 0..63
        int col4 = idx & 31;             // float4 slot
        const float* src = (row < BM)
            ? (x + (size_t)(R0 + row) * D_DIM + col4 * 4)
            : (y + (size_t)(C0 + row - BM) * D_DIM + col4 * 4);
        float4 v = *reinterpret_cast<const float4*>(src);
        *reinterpret_cast<float4*>(&sm[row * LDW + col4 * 4]) = v;
    }
    __syncthreads();

    const u64 NEG1 = 0xBF800000BF800000ULL;   // (-1.f, -1.f)
    const u64 ABSM = 0x7FFFFFFF7FFFFFFFULL;   // packed abs mask

    u64 acc1[4][2];   // packed L1 sums
    u64 acc2[4][2];   // packed sum of squares
    #pragma unroll
    for (int i = 0; i < 4; i++)
        #pragma unroll
        for (int j = 0; j < 2; j++) { acc1[i][j] = 0ULL; acc2[i][j] = 0ULL; }

    #pragma unroll 4
    for (int dd = 0; dd < D_DIM; dd += 4) {
        ull2 xv[4], yv[2];
        #pragma unroll
        for (int i = 0; i < 4; i++)
            xv[i] = *reinterpret_cast<const ull2*>(&xs[(ty + 8 * i) * LDW + dd]);
        #pragma unroll
        for (int j = 0; j < 2; j++)
            yv[j] = *reinterpret_cast<const ull2*>(&ys[(tx + 16 * j) * LDW + dd]);

        #pragma unroll
        for (int i = 0; i < 4; i++) {
            #pragma unroll
            for (int j = 0; j < 2; j++) {
                u64 dA = ffma2(yv[j].x, NEG1, xv[i].x);   // x - y (2 lanes)
                u64 dB = ffma2(yv[j].y, NEG1, xv[i].y);
                u64 s  = ffma2(dA, dA, acc2[i][j]);
                acc2[i][j] = ffma2(dB, dB, s);
                u64 ab = fadd2(dA & ABSM, dB & ABSM);     // 2x LOP3 (alu) + FADD2
                acc1[i][j] = fadd2(acc1[i][j], ab);
            }
        }
    }

    // ---- epilogue: cos / p1 / p2 ----
    #pragma unroll
    for (int i = 0; i < 4; i++) {
        int gr = R0 + ty + 8 * i;
        float xsq = g_xsq[gr];
        float xrn = g_xrn[gr];
        #pragma unroll
        for (int j = 0; j < 2; j++) {
            int gc = C0 + tx + 16 * j;
            float s2 = f2lo(acc2[i][j]) + f2hi(acc2[i][j]);
            float s1 = f2lo(acc1[i][j]) + f2hi(acc1[i][j]);
            float p2 = sqrtf(fmaxf(s2, 0.0f));
            float dot = 0.5f * (xsq + g_ysq[gc] - s2);
            float cosv = dot * xrn * g_yrn[gc];
            size_t idx = ((size_t)gr * C_TOTAL + gc) * 3;
            out[idx + 0] = cosv;
            out[idx + 1] = s1;
            out[idx + 2] = p2;
        }
    }
}

extern "C" void kernel_launch(void* const* d_in, const int* in_sizes, int n_in,
                              void* d_out, int out_size) {
    const float* x = (const float*)d_in[0];
    const float* y = (const float*)d_in[1];
    float* out = (float*)d_out;

    norms_kernel<<<(2560 * 32 + 255) / 256, 256>>>(x, y);

    dim3 grid(R_TOTAL / BM, C_TOTAL / BN);   // 64 x 16 = 1024 blocks
    dist_kernel<<<grid, 128>>>(x, y, out);
}

// round 5
// speedup vs baseline: 1.3600x; 1.3600x over previous
#include <cuda_runtime.h>
#include <cstdint>

// x [4,512,128] f32, y [512,128] f32 -> out [4,512,512,3] f32 (cos, L1, L2)
#define R_TOTAL 2048
#define C_TOTAL 512
#define D_DIM   128
#define NDD2    (D_DIM / 2)     // 64 packed-pair steps

#define BM 64                   // x rows per block
#define BN 32                   // y rows per block
#define XTS 65                  // xsT row stride in u64 ([dd2][row=64]+1 pad)
#define YTS 34                  // ysT row stride in u64 ([dd2][row=32]+2 pad, keeps 16B align)
#define SMEM_BYTES ((NDD2 * XTS + NDD2 * YTS) * 8)   // 33280 + 17408 = 50688 B

typedef unsigned long long u64;
struct __align__(16) ull2 { u64 x, y; };

// ---------------- precomputed norms ----------------
__device__ float g_xsq[R_TOTAL];
__device__ float g_xrn[R_TOTAL];
__device__ float g_ysq[C_TOTAL];
__device__ float g_yrn[C_TOTAL];

__global__ void norms_kernel(const float* __restrict__ x,
                             const float* __restrict__ y) {
    int w    = (blockIdx.x * blockDim.x + threadIdx.x) >> 5;
    int lane = threadIdx.x & 31;
    if (w >= R_TOTAL + C_TOTAL) return;
    const float* p = (w < R_TOTAL) ? (x + (size_t)w * D_DIM)
                                   : (y + (size_t)(w - R_TOTAL) * D_DIM);
    float4 v = reinterpret_cast<const float4*>(p)[lane];
    float s = v.x * v.x + v.y * v.y + v.z * v.z + v.w * v.w;
    #pragma unroll
    for (int o = 16; o > 0; o >>= 1) s += __shfl_xor_sync(0xFFFFFFFFu, s, o);
    if (lane == 0) {
        float r = rsqrtf(s);
        if (w < R_TOTAL) { g_xsq[w] = s; g_xrn[w] = r; }
        else             { g_ysq[w - R_TOTAL] = s; g_yrn[w - R_TOTAL] = r; }
    }
}

// ---------------- packed f32x2 helpers ----------------
__device__ __forceinline__ u64 ffma2(u64 a, u64 b, u64 c) {
    u64 d;
    asm("fma.rn.f32x2 %0, %1, %2, %3;" : "=l"(d) : "l"(a), "l"(b), "l"(c));
    return d;
}
__device__ __forceinline__ u64 fadd2(u64 a, u64 b) {
    u64 d;
    asm("add.rn.f32x2 %0, %1, %2;" : "=l"(d) : "l"(a), "l"(b));
    return d;
}
__device__ __forceinline__ float f2lo(u64 d) { return __uint_as_float((unsigned)(d & 0xFFFFFFFFu)); }
__device__ __forceinline__ float f2hi(u64 d) { return __uint_as_float((unsigned)(d >> 32)); }
__device__ __forceinline__ u64 pack2(float lo, float hi) {
    return ((u64)__float_as_uint(hi) << 32) | (u64)__float_as_uint(lo);
}

// ---------------- main distance kernel ----------------
// 256 threads: tx = t&15 -> cols {2tx, 2tx+1}; ty = t>>4 -> rows ty+16i (i<4)
__global__ void __launch_bounds__(256, 3)
dist_kernel(const float* __restrict__ x, const float* __restrict__ y,
            float* __restrict__ out) {
    extern __shared__ __align__(16) u64 sm64[];
    u64* xsT = sm64;                    // [NDD2][XTS]
    u64* ysT = sm64 + NDD2 * XTS;      // [NDD2][YTS]

    const int R0 = blockIdx.x * BM;     // grid.x = 32
    const int C0 = blockIdx.y * BN;     // grid.y = 16
    const int t  = threadIdx.x;
    const int tx = t & 15;
    const int ty = t >> 4;

    // ---- stage x tile (64 rows x 128) transposed-packed: 8 float4 per thread
    #pragma unroll
    for (int s = 0; s < 8; s++) {
        int idx  = t + 256 * s;         // 0..2047
        int row  = idx >> 5;            // 0..63
        int col4 = idx & 31;
        float4 v = *reinterpret_cast<const float4*>(
            x + (size_t)(R0 + row) * D_DIM + col4 * 4);
        xsT[(2 * col4) * XTS + row]     = pack2(v.x, v.y);
        xsT[(2 * col4 + 1) * XTS + row] = pack2(v.z, v.w);
    }
    // ---- stage y tile (32 rows x 128): 4 float4 per thread
    #pragma unroll
    for (int s = 0; s < 4; s++) {
        int idx  = t + 256 * s;         // 0..1023
        int row  = idx >> 5;            // 0..31
        int col4 = idx & 31;
        float4 v = *reinterpret_cast<const float4*>(
            y + (size_t)(C0 + row) * D_DIM + col4 * 4);
        ysT[(2 * col4) * YTS + row]     = pack2(v.x, v.y);
        ysT[(2 * col4 + 1) * YTS + row] = pack2(v.z, v.w);
    }
    __syncthreads();

    const u64 NEG1 = 0xBF800000BF800000ULL;   // (-1.f, -1.f)
    const u64 ABSM = 0x7FFFFFFF7FFFFFFFULL;   // packed abs mask

    u64 acc1[4][2];   // packed L1 sums   (rows i, cols j)
    u64 acc2[4][2];   // packed sum of squares
    #pragma unroll
    for (int i = 0; i < 4; i++)
        #pragma unroll
        for (int j = 0; j < 2; j++) { acc1[i][j] = 0ULL; acc2[i][j] = 0ULL; }

    const u64*  px = xsT + ty;                                    // rows ty+16i
    const ull2* py = reinterpret_cast<const ull2*>(ysT + 2 * tx); // cols 2tx,2tx+1

    #pragma unroll 8
    for (int dd2 = 0; dd2 < NDD2; dd2++) {
        u64 xv[4];
        #pragma unroll
        for (int i = 0; i < 4; i++) xv[i] = px[16 * i];           // LDS.64 broadcast
        ull2 yv = *py;                                            // LDS.128 contiguous

        #pragma unroll
        for (int i = 0; i < 4; i++) {
            u64 d0 = ffma2(yv.x, NEG1, xv[i]);   // x - y (2 D-lanes), col 2tx
            u64 d1 = ffma2(yv.y, NEG1, xv[i]);   // col 2tx+1
            acc2[i][0] = ffma2(d0, d0, acc2[i][0]);
            acc2[i][1] = ffma2(d1, d1, acc2[i][1]);
            acc1[i][0] = fadd2(acc1[i][0], d0 & ABSM);
            acc1[i][1] = fadd2(acc1[i][1], d1 & ABSM);
        }

        px += XTS;
        py += YTS / 2;
    }

    // ---- epilogue: cos / p1 / p2 ----
    #pragma unroll
    for (int i = 0; i < 4; i++) {
        int gr = R0 + ty + 16 * i;
        float xsq = g_xsq[gr];
        float xrn = g_xrn[gr];
        #pragma unroll
        for (int j = 0; j < 2; j++) {
            int gc = C0 + 2 * tx + j;
            float s2 = f2lo(acc2[i][j]) + f2hi(acc2[i][j]);
            float s1 = f2lo(acc1[i][j]) + f2hi(acc1[i][j]);
            float p2 = sqrtf(fmaxf(s2, 0.0f));
            float dot = 0.5f * (xsq + g_ysq[gc] - s2);
            float cosv = dot * xrn * g_yrn[gc];
            size_t idx = ((size_t)gr * C_TOTAL + gc) * 3;
            out[idx + 0] = cosv;
            out[idx + 1] = s1;
            out[idx + 2] = p2;
        }
    }
}

extern "C" void kernel_launch(void* const* d_in, const int* in_sizes, int n_in,
                              void* d_out, int out_size) {
    const float* x = (const float*)d_in[0];
    const float* y = (const float*)d_in[1];
    float* out = (float*)d_out;

    cudaFuncSetAttribute(dist_kernel,
                         cudaFuncAttributeMaxDynamicSharedMemorySize, SMEM_BYTES);

    norms_kernel<<<(2560 * 32 + 255) / 256, 256>>>(x, y);

    dim3 grid(R_TOTAL / BM, C_TOTAL / BN);   // 32 x 16 = 512 blocks
    dist_kernel<<<grid, 256, SMEM_BYTES>>>(x, y, out);
}